// round 5
// baseline (speedup 1.0000x reference)
#include <cuda_runtime.h>

#define NN 8
#define CC 640
#define HH 48
#define WW 48
#define KK 9
#define HT 4                  // output rows per thread (rolling 3-row window)
#define WQ 12                 // w-quads per row (48/4)
#define TY 16
#define THREADS (WQ * TY)     // 192
#define CB 2                  // channels per thread
#define CBLK (TY * CB)        // 32 channels per block

__global__ __launch_bounds__(THREADS) void dyn_conv_kernel(
    const float* __restrict__ q,
    const float* __restrict__ df,
    float* __restrict__ out,
    int tail_n4)
{
    // ---- fused tail-zero slice ----
    if (blockIdx.y == CC / CBLK) {
        const int q_elems = NN * CC * HH * WW;
        float4* p = reinterpret_cast<float4*>(out + q_elems);
        const int tid    = threadIdx.y * WQ + threadIdx.x;
        const int gtid   = (blockIdx.z * gridDim.x + blockIdx.x) * THREADS + tid;
        const int stride = gridDim.x * gridDim.z * THREADS;
        for (int i = gtid; i < tail_n4; i += stride)
            p[i] = make_float4(0.f, 0.f, 0.f, 0.f);
        return;
    }

    const int h0 = blockIdx.x * HT;
    const int c0 = blockIdx.y * CBLK;
    const int n  = blockIdx.z;

    const int tx = threadIdx.x;        // 0..11
    const int ty = threadIdx.y;        // 0..15
    const int w4 = tx * 4;

    const float* qb[CB];
    float*       ob[CB];
#pragma unroll
    for (int cb = 0; cb < CB; cb++) {
        const int c = c0 + ty + cb * TY;
        qb[cb] = q   + ((size_t)(n * CC + c) * HH) * WW;
        ob[cb] = out + (((size_t)(n * CC + c) * HH) + h0) * WW + w4;
    }

    // Filter pointer: df[n, h0*W + w4, 0] — each output row needs 36 contiguous
    // floats df[(h*W+w4)*9 .. +35], 144B, 16B-aligned (tx*144 from row base).
    const float* dfp = df + ((size_t)(n * HH + h0) * WW + (size_t)w4) * KK;

    // rolling 3-row window per channel; [0..5] covers w4-1 .. w4+4 (zero-padded)
    float rows[CB][3][6];

    auto load_rows = [&](int s, int hh) {
        const bool ok = (hh >= 0) && (hh < HH);
#pragma unroll
        for (int cb = 0; cb < CB; cb++) {
            float* r = rows[cb][s];
            if (!ok) {
#pragma unroll
                for (int j = 0; j < 6; j++) r[j] = 0.0f;
            } else {
                const float* row = qb[cb] + hh * WW;
                float4 v = *reinterpret_cast<const float4*>(row + w4);  // 16B aligned
                r[1] = v.x; r[2] = v.y; r[3] = v.z; r[4] = v.w;
                r[0] = (w4 > 0)      ? row[w4 - 1] : 0.0f;
                r[5] = (w4 + 4 < WW) ? row[w4 + 4] : 0.0f;
            }
        }
    };

    load_rows(0, h0 - 1);
    load_rows(1, h0);

#pragma unroll
    for (int i = 0; i < HT; i++) {
        // Load this output row's filter block: 9 x float4 = 36 floats, coalesced.
        // Register "transpose": ff[j*9+k] = filter tap k for output w4+j.
        float ff[4 * KK];
        {
            const float4* fp =
                reinterpret_cast<const float4*>(dfp + (size_t)i * WW * KK);
#pragma unroll
            for (int v = 0; v < KK; v++) {
                float4 t = fp[v];
                ff[v * 4 + 0] = t.x;
                ff[v * 4 + 1] = t.y;
                ff[v * 4 + 2] = t.z;
                ff[v * 4 + 3] = t.w;
            }
        }

        load_rows((i + 2) % 3, h0 + i + 1);

#pragma unroll
        for (int cb = 0; cb < CB; cb++) {
            float acc0 = 0.f, acc1 = 0.f, acc2 = 0.f, acc3 = 0.f;
#pragma unroll
            for (int di = 0; di < 3; di++) {
                const float* rr = rows[cb][(i + di) % 3];  // constant after unroll
#pragma unroll
                for (int dj = 0; dj < 3; dj++) {
                    const int k = di * 3 + dj;
                    acc0 = fmaf(rr[dj + 0], ff[0 * KK + k], acc0);
                    acc1 = fmaf(rr[dj + 1], ff[1 * KK + k], acc1);
                    acc2 = fmaf(rr[dj + 2], ff[2 * KK + k], acc2);
                    acc3 = fmaf(rr[dj + 3], ff[3 * KK + k], acc3);
                }
            }
            float4 o;
            o.x = fmaxf(acc0, 0.0f);
            o.y = fmaxf(acc1, 0.0f);
            o.z = fmaxf(acc2, 0.0f);
            o.w = fmaxf(acc3, 0.0f);
            *reinterpret_cast<float4*>(ob[cb] + i * WW) = o;
        }
    }
}

extern "C" void kernel_launch(void* const* d_in, const int* in_sizes, int n_in,
                              void* d_out, int out_size)
{
    const float* q  = (const float*)d_in[0];
    const float* df = (const float*)d_in[1];
    const int q_elems = NN * CC * HH * WW;
    if (n_in >= 2 && in_sizes[0] != q_elems) {
        const float* t = q; q = df; df = t;
    }

    float* out = (float*)d_out;

    const int tail    = out_size - q_elems;
    const int tail_n4 = (tail > 0) ? tail / 4 : 0;

    dim3 blk(WQ, TY);                                          // 192 threads
    dim3 grd(HH / HT, CC / CBLK + (tail_n4 > 0 ? 1 : 0), NN);  // 12 x 21 x 8
    dyn_conv_kernel<<<grd, blk>>>(q, df, out, tail_n4);
}

// round 6
// speedup vs baseline: 1.0469x; 1.0469x over previous
#include <cuda_runtime.h>

#define NN 8
#define CC 640
#define HH 48
#define WW 48
#define KK 9
#define HT 4                  // output rows per thread (rolling 3-row window)
#define WQ 12                 // w-quads per row (48/4)
#define TY 16
#define THREADS (WQ * TY)     // 192
#define CB 2                  // channels per thread
#define CBLK (TY * CB)        // 32 channels per block

__global__ __launch_bounds__(THREADS, 6) void dyn_conv_kernel(
    const float* __restrict__ q,
    const float* __restrict__ df,
    float* __restrict__ out,
    int tail_n4)
{
    // ---- fused tail-zero slice ----
    if (blockIdx.y == CC / CBLK) {
        const int q_elems = NN * CC * HH * WW;
        float4* p = reinterpret_cast<float4*>(out + q_elems);
        const int tid    = threadIdx.y * WQ + threadIdx.x;
        const int gtid   = (blockIdx.z * gridDim.x + blockIdx.x) * THREADS + tid;
        const int stride = gridDim.x * gridDim.z * THREADS;
        for (int i = gtid; i < tail_n4; i += stride)
            p[i] = make_float4(0.f, 0.f, 0.f, 0.f);
        return;
    }

    __shared__ float fs[HT][KK][WW];   // filter transposed: [h][k][w]

    const int h0 = blockIdx.x * HT;
    const int c0 = blockIdx.y * CBLK;
    const int n  = blockIdx.z;

    const int tx  = threadIdx.x;       // 0..11
    const int ty  = threadIdx.y;       // 0..15
    const int tid = ty * WQ + tx;

    // Cooperative filter load: HT*W*K = 1728 floats; 1728/192 = 9 iterations.
    {
        const float* dfr = df + (size_t)(n * HH + h0) * WW * KK;
#pragma unroll
        for (int it = 0; it < (HT * WW * KK) / THREADS; it++) {
            int i   = tid + it * THREADS;
            int hi  = i / (WW * KK);
            int rem = i - hi * (WW * KK);
            int w   = rem / KK;
            int k   = rem - w * KK;
            fs[hi][k][w] = dfr[i];
        }
    }
    __syncthreads();

    const int w4 = tx * 4;

    const float* qb[CB];
    float*       ob[CB];
#pragma unroll
    for (int cb = 0; cb < CB; cb++) {
        const int c = c0 + ty + cb * TY;
        qb[cb] = q   + ((size_t)(n * CC + c) * HH) * WW;
        ob[cb] = out + (((size_t)(n * CC + c) * HH) + h0) * WW + w4;
    }

    // rolling 3-row window per channel; [0..5] covers w4-1 .. w4+4 (zero-padded)
    float rows[CB][3][6];

    auto load_rows = [&](int s, int hh) {
        const bool ok = (hh >= 0) && (hh < HH);
#pragma unroll
        for (int cb = 0; cb < CB; cb++) {
            float* r = rows[cb][s];
            if (!ok) {
#pragma unroll
                for (int j = 0; j < 6; j++) r[j] = 0.0f;
            } else {
                const float* row = qb[cb] + hh * WW;
                float4 v = *reinterpret_cast<const float4*>(row + w4);  // 16B aligned
                r[1] = v.x; r[2] = v.y; r[3] = v.z; r[4] = v.w;
                r[0] = (w4 > 0)      ? row[w4 - 1] : 0.0f;
                r[5] = (w4 + 4 < WW) ? row[w4 + 4] : 0.0f;
            }
        }
    };

    load_rows(0, h0 - 1);
    load_rows(1, h0);

#pragma unroll
    for (int i = 0; i < HT; i++) {
        load_rows((i + 2) % 3, h0 + i + 1);

        // k-outer / channel-inner: only ONE filter float4 live at a time.
        float acc[CB][4];
#pragma unroll
        for (int cb = 0; cb < CB; cb++)
#pragma unroll
            for (int j = 0; j < 4; j++) acc[cb][j] = 0.0f;

#pragma unroll
        for (int di = 0; di < 3; di++) {
#pragma unroll
            for (int dj = 0; dj < 3; dj++) {
                const int k = di * 3 + dj;
                float4 f = *reinterpret_cast<const float4*>(&fs[i][k][w4]);
#pragma unroll
                for (int cb = 0; cb < CB; cb++) {
                    const float* rr = rows[cb][(i + di) % 3];  // const after unroll
                    acc[cb][0] = fmaf(rr[dj + 0], f.x, acc[cb][0]);
                    acc[cb][1] = fmaf(rr[dj + 1], f.y, acc[cb][1]);
                    acc[cb][2] = fmaf(rr[dj + 2], f.z, acc[cb][2]);
                    acc[cb][3] = fmaf(rr[dj + 3], f.w, acc[cb][3]);
                }
            }
        }

#pragma unroll
        for (int cb = 0; cb < CB; cb++) {
            float4 o;
            o.x = fmaxf(acc[cb][0], 0.0f);
            o.y = fmaxf(acc[cb][1], 0.0f);
            o.z = fmaxf(acc[cb][2], 0.0f);
            o.w = fmaxf(acc[cb][3], 0.0f);
            *reinterpret_cast<float4*>(ob[cb] + i * WW) = o;
        }
    }
}

extern "C" void kernel_launch(void* const* d_in, const int* in_sizes, int n_in,
                              void* d_out, int out_size)
{
    const float* q  = (const float*)d_in[0];
    const float* df = (const float*)d_in[1];
    const int q_elems = NN * CC * HH * WW;
    if (n_in >= 2 && in_sizes[0] != q_elems) {
        const float* t = q; q = df; df = t;
    }

    float* out = (float*)d_out;

    const int tail    = out_size - q_elems;
    const int tail_n4 = (tail > 0) ? tail / 4 : 0;

    dim3 blk(WQ, TY);                                          // 192 threads
    dim3 grd(HH / HT, CC / CBLK + (tail_n4 > 0 ? 1 : 0), NN);  // 12 x 21 x 8
    dyn_conv_kernel<<<grd, blk>>>(q, df, out, tail_n4);
}

// round 7
// speedup vs baseline: 1.1317x; 1.0810x over previous
#include <cuda_runtime.h>

#define NN 8
#define CC 640
#define HH 48
#define WW 48
#define KK 9
#define WQ 12                 // w-quads per row
#define TYB 8                 // h-pairs per block (band = 16 rows)
#define THREADS (WQ * TYB)    // 96
#define CG 8                  // channels looped per block

__global__ __launch_bounds__(THREADS) void dyn_conv_kernel(
    const float* __restrict__ q,
    const float* __restrict__ df,
    float* __restrict__ out,
    int tail_n4)
{
    // ---- fused tail-zero slice ----
    if (blockIdx.y == CC / CG) {
        const int q_elems = NN * CC * HH * WW;
        float4* p = reinterpret_cast<float4*>(out + q_elems);
        const int tid    = threadIdx.y * WQ + threadIdx.x;
        const int gtid   = (blockIdx.z * gridDim.x + blockIdx.x) * THREADS + tid;
        const int stride = gridDim.x * gridDim.z * THREADS;
        for (int i = gtid; i < tail_n4; i += stride)
            p[i] = make_float4(0.f, 0.f, 0.f, 0.f);
        return;
    }

    const int tx = threadIdx.x;                    // 0..11
    const int ty = threadIdx.y;                    // 0..7
    const int h0 = blockIdx.x * (2 * TYB) + ty * 2; // two output rows h0, h0+1
    const int c0 = blockIdx.y * CG;
    const int n  = blockIdx.z;
    const int w4 = tx * 4;

    // Filter for this thread's fixed (h0..h0+1, w4..w4+3) tile, in REGISTERS.
    // ff[r][j*9+k] = tap k for output (h0+r, w4+j). Each row's 36 floats are
    // contiguous at df[((n*H+h)*W + w4)*9], 144B, 16B-aligned -> 9 LDG.128.
    float ff[2][36];
#pragma unroll
    for (int r = 0; r < 2; r++) {
        const float4* fp = reinterpret_cast<const float4*>(
            df + ((size_t)(n * HH + h0 + r) * WW + (size_t)w4) * KK);
#pragma unroll
        for (int v = 0; v < 9; v++) {
            float4 t = fp[v];
            ff[r][v * 4 + 0] = t.x;
            ff[r][v * 4 + 1] = t.y;
            ff[r][v * 4 + 2] = t.z;
            ff[r][v * 4 + 3] = t.w;
        }
    }

    const float* qb = q   + (size_t)(n * CC + c0) * HH * WW;
    float*       ob = out + ((size_t)(n * CC + c0) * HH + h0) * WW + w4;

    const bool top_ok = (h0 - 1) >= 0;       // false only for bx==0, ty==0
    const bool bot_ok = (h0 + 2) < HH;       // false only for bx==2, ty==7

#pragma unroll 2
    for (int c = 0; c < CG; c++) {
        // Input rows h0-1 .. h0+2, each 6 wide: [0..5] covers w4-1 .. w4+4.
        float rows[4][6];
#pragma unroll
        for (int rr = 0; rr < 4; rr++) {
            const bool ok = (rr == 0) ? top_ok : (rr == 3) ? bot_ok : true;
            float* r = rows[rr];
            if (!ok) {
#pragma unroll
                for (int j = 0; j < 6; j++) r[j] = 0.0f;
            } else {
                const float* row = qb + (h0 - 1 + rr) * WW;
                float4 v = *reinterpret_cast<const float4*>(row + w4);
                r[1] = v.x; r[2] = v.y; r[3] = v.z; r[4] = v.w;
                r[0] = (w4 > 0)      ? row[w4 - 1] : 0.0f;
                r[5] = (w4 + 4 < WW) ? row[w4 + 4] : 0.0f;
            }
        }

        float acc[2][4];
#pragma unroll
        for (int r = 0; r < 2; r++)
#pragma unroll
            for (int j = 0; j < 4; j++) acc[r][j] = 0.0f;

#pragma unroll
        for (int r = 0; r < 2; r++)
#pragma unroll
            for (int di = 0; di < 3; di++) {
                const float* rr = rows[r + di];
#pragma unroll
                for (int dj = 0; dj < 3; dj++) {
                    const int k = di * 3 + dj;
                    acc[r][0] = fmaf(rr[dj + 0], ff[r][0 * KK + k], acc[r][0]);
                    acc[r][1] = fmaf(rr[dj + 1], ff[r][1 * KK + k], acc[r][1]);
                    acc[r][2] = fmaf(rr[dj + 2], ff[r][2 * KK + k], acc[r][2]);
                    acc[r][3] = fmaf(rr[dj + 3], ff[r][3 * KK + k], acc[r][3]);
                }
            }

#pragma unroll
        for (int r = 0; r < 2; r++) {
            float4 o;
            o.x = fmaxf(acc[r][0], 0.0f);
            o.y = fmaxf(acc[r][1], 0.0f);
            o.z = fmaxf(acc[r][2], 0.0f);
            o.w = fmaxf(acc[r][3], 0.0f);
            *reinterpret_cast<float4*>(ob + r * WW) = o;
        }

        qb += HH * WW;
        ob += HH * WW;
    }
}

extern "C" void kernel_launch(void* const* d_in, const int* in_sizes, int n_in,
                              void* d_out, int out_size)
{
    const float* q  = (const float*)d_in[0];
    const float* df = (const float*)d_in[1];
    const int q_elems = NN * CC * HH * WW;
    if (n_in >= 2 && in_sizes[0] != q_elems) {
        const float* t = q; q = df; df = t;
    }

    float* out = (float*)d_out;

    const int tail    = out_size - q_elems;
    const int tail_n4 = (tail > 0) ? tail / 4 : 0;

    dim3 blk(WQ, TYB);                                        // 96 threads
    dim3 grd(HH / (2 * TYB), CC / CG + (tail_n4 > 0 ? 1 : 0), NN);  // 3 x 81 x 8
    dyn_conv_kernel<<<grd, blk>>>(q, df, out, tail_n4);
}

// round 8
// speedup vs baseline: 1.1384x; 1.0059x over previous
#include <cuda_runtime.h>

#define NN 8
#define CC 640
#define HH 48
#define WW 48
#define KK 9
#define WQ 12                 // w-quads per row
#define TYB 8                 // h-pairs per block (band = 16 rows)
#define THREADS (WQ * TYB)    // 96
#define CG 8                  // channels looped per block

__global__ __launch_bounds__(THREADS) void dyn_conv_kernel(
    const float* __restrict__ q,
    const float* __restrict__ df,
    float* __restrict__ out,
    int tail_n4)
{
    // ---- fused tail-zero slice ----
    if (blockIdx.y == CC / CG) {
        const int q_elems = NN * CC * HH * WW;
        float4* p = reinterpret_cast<float4*>(out + q_elems);
        const int tid    = threadIdx.y * WQ + threadIdx.x;
        const int gtid   = (blockIdx.z * gridDim.x + blockIdx.x) * THREADS + tid;
        const int stride = gridDim.x * gridDim.z * THREADS;
        for (int i = gtid; i < tail_n4; i += stride)
            p[i] = make_float4(0.f, 0.f, 0.f, 0.f);
        return;
    }

    const int tx = threadIdx.x;                     // 0..11
    const int ty = threadIdx.y;                     // 0..7
    const int h0 = blockIdx.x * (2 * TYB) + ty * 2; // output rows h0, h0+1
    const int c0 = blockIdx.y * CG;
    const int n  = blockIdx.z;
    const int w4 = tx * 4;

    // Filter for this thread's fixed (h0..h0+1, w4..w4+3) tile, in REGISTERS.
    // ff[r][j*9+k] = tap k for output (h0+r, w4+j); 9 coalesced LDG.128 per row.
    float ff[2][36];
#pragma unroll
    for (int r = 0; r < 2; r++) {
        const float4* fp = reinterpret_cast<const float4*>(
            df + ((size_t)(n * HH + h0 + r) * WW + (size_t)w4) * KK);
#pragma unroll
        for (int v = 0; v < 9; v++) {
            float4 t = fp[v];
            ff[r][v * 4 + 0] = t.x;
            ff[r][v * 4 + 1] = t.y;
            ff[r][v * 4 + 2] = t.z;
            ff[r][v * 4 + 3] = t.w;
        }
    }

    const bool ok0 = (h0 - 1) >= 0;   // top input row valid
    const bool ok3 = (h0 + 2) < HH;   // bottom input row valid
    const bool lok = (w4 > 0);        // left edge exists
    const bool rok = (w4 + 4 < WW);   // right edge exists

    const float* qb = q   + ((size_t)(n * CC + c0) * HH + h0) * WW + w4; // -> row h0
    float*       ob = out + ((size_t)(n * CC + c0) * HH + h0) * WW + w4;

    const float4 z4 = make_float4(0.f, 0.f, 0.f, 0.f);

    // 1-deep software pipeline on the 4 main vectors of the NEXT channel.
    float4 pf[4];
#pragma unroll
    for (int rr = 0; rr < 4; rr++) {
        const bool ok = (rr == 0) ? ok0 : (rr == 3) ? ok3 : true;
        pf[rr] = ok ? *reinterpret_cast<const float4*>(qb + (rr - 1) * WW) : z4;
    }

    for (int c = 0; c < CG; c++) {
        const float* qc = qb;         // current channel (points at row h0, col w4)
        qb += HH * WW;

        float4 cur[4];
#pragma unroll
        for (int rr = 0; rr < 4; rr++) cur[rr] = pf[rr];

        // Prefetch next channel's main vectors NOW — consumed ~80 instrs later.
        if (c + 1 < CG) {
#pragma unroll
            for (int rr = 0; rr < 4; rr++) {
                const bool ok = (rr == 0) ? ok0 : (rr == 3) ? ok3 : true;
                pf[rr] = ok ? *reinterpret_cast<const float4*>(qb + (rr - 1) * WW) : z4;
            }
        }

        // Edge scalars for current channel — same L1 lines the vector loads warmed.
        float e0[4], e1[4];
#pragma unroll
        for (int rr = 0; rr < 4; rr++) {
            const bool ok = (rr == 0) ? ok0 : (rr == 3) ? ok3 : true;
            e0[rr] = (ok && lok) ? qc[(rr - 1) * WW - 1] : 0.f;
            e1[rr] = (ok && rok) ? qc[(rr - 1) * WW + 4] : 0.f;
        }

        float acc[2][4];
#pragma unroll
        for (int r = 0; r < 2; r++)
#pragma unroll
            for (int j = 0; j < 4; j++) acc[r][j] = 0.0f;

#pragma unroll
        for (int r = 0; r < 2; r++) {
#pragma unroll
            for (int di = 0; di < 3; di++) {
                const int rr = r + di;
                float rowv[6];
                rowv[0] = e0[rr];
                rowv[1] = cur[rr].x; rowv[2] = cur[rr].y;
                rowv[3] = cur[rr].z; rowv[4] = cur[rr].w;
                rowv[5] = e1[rr];
#pragma unroll
                for (int dj = 0; dj < 3; dj++) {
                    const int k = di * 3 + dj;
                    acc[r][0] = fmaf(rowv[dj + 0], ff[r][0 * KK + k], acc[r][0]);
                    acc[r][1] = fmaf(rowv[dj + 1], ff[r][1 * KK + k], acc[r][1]);
                    acc[r][2] = fmaf(rowv[dj + 2], ff[r][2 * KK + k], acc[r][2]);
                    acc[r][3] = fmaf(rowv[dj + 3], ff[r][3 * KK + k], acc[r][3]);
                }
            }
        }

#pragma unroll
        for (int r = 0; r < 2; r++) {
            float4 o;
            o.x = fmaxf(acc[r][0], 0.0f);
            o.y = fmaxf(acc[r][1], 0.0f);
            o.z = fmaxf(acc[r][2], 0.0f);
            o.w = fmaxf(acc[r][3], 0.0f);
            *reinterpret_cast<float4*>(ob + r * WW) = o;
        }
        ob += HH * WW;
    }
}

extern "C" void kernel_launch(void* const* d_in, const int* in_sizes, int n_in,
                              void* d_out, int out_size)
{
    const float* q  = (const float*)d_in[0];
    const float* df = (const float*)d_in[1];
    const int q_elems = NN * CC * HH * WW;
    if (n_in >= 2 && in_sizes[0] != q_elems) {
        const float* t = q; q = df; df = t;
    }

    float* out = (float*)d_out;

    const int tail    = out_size - q_elems;
    const int tail_n4 = (tail > 0) ? tail / 4 : 0;

    dim3 blk(WQ, TYB);                                              // 96 threads
    dim3 grd(HH / (2 * TYB), CC / CG + (tail_n4 > 0 ? 1 : 0), NN);  // 3 x 81 x 8
    dyn_conv_kernel<<<grd, blk>>>(q, df, out, tail_n4);
}

// round 9
// speedup vs baseline: 1.2008x; 1.0549x over previous
#include <cuda_runtime.h>

#define NN 8
#define CC 640
#define HH 48
#define WW 48
#define KK 9
#define WQ 12                 // w-quads per row
#define TYB 8                 // h-pairs per block (band = 16 rows)
#define THREADS (WQ * TYB)    // 96
#define CG 8                  // channels looped per block

__global__ __launch_bounds__(THREADS) void dyn_conv_kernel(
    const float* __restrict__ q,
    const float* __restrict__ df,
    float* __restrict__ out,
    int tail_n4)
{
    // ---- fused tail-zero slice ----
    if (blockIdx.y == CC / CG) {
        const int q_elems = NN * CC * HH * WW;
        float4* p = reinterpret_cast<float4*>(out + q_elems);
        const int tid    = threadIdx.y * WQ + threadIdx.x;
        const int gtid   = (blockIdx.z * gridDim.x + blockIdx.x) * THREADS + tid;
        const int stride = gridDim.x * gridDim.z * THREADS;
        for (int i = gtid; i < tail_n4; i += stride)
            p[i] = make_float4(0.f, 0.f, 0.f, 0.f);
        return;
    }

    const int tx   = threadIdx.x;                     // 0..11
    const int ty   = threadIdx.y;                     // 0..7
    const int tid  = ty * WQ + tx;
    const int lane = tid & 31;
    const int h0   = blockIdx.x * (2 * TYB) + ty * 2; // output rows h0, h0+1
    const int c0   = blockIdx.y * CG;
    const int n    = blockIdx.z;
    const int w4   = tx * 4;

    // Filter for this thread's fixed (h0..h0+1, w4..w4+3) tile, in REGISTERS.
    float ff[2][36];
#pragma unroll
    for (int r = 0; r < 2; r++) {
        const float4* fp = reinterpret_cast<const float4*>(
            df + ((size_t)(n * HH + h0 + r) * WW + (size_t)w4) * KK);
#pragma unroll
        for (int v = 0; v < 9; v++) {
            float4 t = fp[v];
            ff[r][v * 4 + 0] = t.x;
            ff[r][v * 4 + 1] = t.y;
            ff[r][v * 4 + 2] = t.z;
            ff[r][v * 4 + 3] = t.w;
        }
    }

    const bool ok0 = (h0 - 1) >= 0;   // top input row valid
    const bool ok3 = (h0 + 2) < HH;   // bottom input row valid
    const bool lok = (w4 > 0);        // left edge exists (image)
    const bool rok = (w4 + 4 < WW);   // right edge exists (image)
    // warp-boundary fixup lanes: row neighbor is in another warp
    const bool lfixlane = (lane == 0)  && lok;
    const bool rfixlane = (lane == 31) && rok;

    const float* qb = q   + ((size_t)(n * CC + c0) * HH + h0) * WW + w4;
    float*       ob = out + ((size_t)(n * CC + c0) * HH + h0) * WW + w4;

    const float4 z4 = make_float4(0.f, 0.f, 0.f, 0.f);

    // 1-deep software pipeline on the 4 input-row vectors of the next channel.
    float4 pf[4];
#pragma unroll
    for (int rr = 0; rr < 4; rr++) {
        const bool ok = (rr == 0) ? ok0 : (rr == 3) ? ok3 : true;
        pf[rr] = ok ? *reinterpret_cast<const float4*>(qb + (rr - 1) * WW) : z4;
    }

    for (int c = 0; c < CG; c++) {
        const float* qc = qb;         // current channel, points at (h0, w4)
        qb += HH * WW;

        float4 cur[4];
#pragma unroll
        for (int rr = 0; rr < 4; rr++) cur[rr] = pf[rr];

        if (c + 1 < CG) {
#pragma unroll
            for (int rr = 0; rr < 4; rr++) {
                const bool ok = (rr == 0) ? ok0 : (rr == 3) ? ok3 : true;
                pf[rr] = ok ? *reinterpret_cast<const float4*>(qb + (rr - 1) * WW) : z4;
            }
        }

        // Edges via intra-warp shuffle; warp-boundary lanes fix up with a
        // single-active-lane LDG (1 wavefront). tx==0 / tx==11 masked to 0.
        float e0[4], e1[4];
#pragma unroll
        for (int rr = 0; rr < 4; rr++) {
            const bool okr = (rr == 0) ? ok0 : (rr == 3) ? ok3 : true;
            float lft = __shfl_up_sync(0xffffffffu, cur[rr].w, 1);
            float rgt = __shfl_down_sync(0xffffffffu, cur[rr].x, 1);
            if (lfixlane) lft = okr ? qc[(rr - 1) * WW - 1] : 0.f;
            if (rfixlane) rgt = okr ? qc[(rr - 1) * WW + 4] : 0.f;
            e0[rr] = lok ? lft : 0.f;
            e1[rr] = rok ? rgt : 0.f;
        }

        float acc[2][4];
#pragma unroll
        for (int r = 0; r < 2; r++)
#pragma unroll
            for (int j = 0; j < 4; j++) acc[r][j] = 0.0f;

#pragma unroll
        for (int r = 0; r < 2; r++) {
#pragma unroll
            for (int di = 0; di < 3; di++) {
                const int rr = r + di;
                float rowv[6];
                rowv[0] = e0[rr];
                rowv[1] = cur[rr].x; rowv[2] = cur[rr].y;
                rowv[3] = cur[rr].z; rowv[4] = cur[rr].w;
                rowv[5] = e1[rr];
#pragma unroll
                for (int dj = 0; dj < 3; dj++) {
                    const int k = di * 3 + dj;
                    acc[r][0] = fmaf(rowv[dj + 0], ff[r][0 * KK + k], acc[r][0]);
                    acc[r][1] = fmaf(rowv[dj + 1], ff[r][1 * KK + k], acc[r][1]);
                    acc[r][2] = fmaf(rowv[dj + 2], ff[r][2 * KK + k], acc[r][2]);
                    acc[r][3] = fmaf(rowv[dj + 3], ff[r][3 * KK + k], acc[r][3]);
                }
            }
        }

#pragma unroll
        for (int r = 0; r < 2; r++) {
            float4 o;
            o.x = fmaxf(acc[r][0], 0.0f);
            o.y = fmaxf(acc[r][1], 0.0f);
            o.z = fmaxf(acc[r][2], 0.0f);
            o.w = fmaxf(acc[r][3], 0.0f);
            *reinterpret_cast<float4*>(ob + r * WW) = o;
        }
        ob += HH * WW;
    }
}

extern "C" void kernel_launch(void* const* d_in, const int* in_sizes, int n_in,
                              void* d_out, int out_size)
{
    const float* q  = (const float*)d_in[0];
    const float* df = (const float*)d_in[1];
    const int q_elems = NN * CC * HH * WW;
    if (n_in >= 2 && in_sizes[0] != q_elems) {
        const float* t = q; q = df; df = t;
    }

    float* out = (float*)d_out;

    const int tail    = out_size - q_elems;
    const int tail_n4 = (tail > 0) ? tail / 4 : 0;

    dim3 blk(WQ, TYB);                                              // 96 threads
    dim3 grd(HH / (2 * TYB), CC / CG + (tail_n4 > 0 ? 1 : 0), NN);  // 3 x 81 x 8
    dyn_conv_kernel<<<grd, blk>>>(q, df, out, tail_n4);
}

// round 10
// speedup vs baseline: 1.2046x; 1.0031x over previous
#include <cuda_runtime.h>

#define NN 8
#define CC 640
#define HH 48
#define WW 48
#define KK 9
#define WQ 12                 // w-quads per row
#define TYB 16                // h-rows per block
#define THREADS (WQ * TYB)    // 192
#define CG 16                 // channels looped per block

__global__ __launch_bounds__(THREADS, 4) void dyn_conv_kernel(
    const float* __restrict__ q,
    const float* __restrict__ df,
    float* __restrict__ out,
    int tail_n4)
{
    // ---- fused tail-zero slice ----
    if (blockIdx.y == CC / CG) {
        const int q_elems = NN * CC * HH * WW;
        float4* p = reinterpret_cast<float4*>(out + q_elems);
        const int tid    = threadIdx.y * WQ + threadIdx.x;
        const int gtid   = (blockIdx.z * gridDim.x + blockIdx.x) * THREADS + tid;
        const int stride = gridDim.x * gridDim.z * THREADS;
        for (int i = gtid; i < tail_n4; i += stride)
            p[i] = make_float4(0.f, 0.f, 0.f, 0.f);
        return;
    }

    const int tx   = threadIdx.x;                 // 0..11
    const int ty   = threadIdx.y;                 // 0..15
    const int tid  = ty * WQ + tx;
    const int lane = tid & 31;
    const int h    = blockIdx.x * TYB + ty;       // output row
    const int c0   = blockIdx.y * CG;
    const int n    = blockIdx.z;
    const int w4   = tx * 4;

    // Filter for this thread's fixed (h, w4..w4+3) tile, in REGISTERS.
    // fl[j*9+k] = tap k for output (h, w4+j); 9 coalesced LDG.128.
    float fl[36];
    {
        const float4* fp = reinterpret_cast<const float4*>(
            df + ((size_t)(n * HH + h) * WW + (size_t)w4) * KK);
#pragma unroll
        for (int v = 0; v < 9; v++) {
            float4 t = fp[v];
            fl[v * 4 + 0] = t.x;
            fl[v * 4 + 1] = t.y;
            fl[v * 4 + 2] = t.z;
            fl[v * 4 + 3] = t.w;
        }
    }

    const bool ok0 = (h - 1) >= 0;    // top input row valid
    const bool ok2 = (h + 1) < HH;    // bottom input row valid
    const bool lok = (w4 > 0);        // left edge exists (image)
    const bool rok = (w4 + 4 < WW);   // right edge exists (image)
    const bool lfixlane = (lane == 0)  && lok;   // row-neighbor in other warp
    const bool rfixlane = (lane == 31) && rok;

    const float* qb = q   + ((size_t)(n * CC + c0) * HH + h) * WW + w4;
    float*       ob = out + ((size_t)(n * CC + c0) * HH + h) * WW + w4;

    const float4 z4 = make_float4(0.f, 0.f, 0.f, 0.f);

    for (int c = 0; c < CG; c++) {
        // 3 input rows h-1, h, h+1 (independent loads -> MLP 3)
        float4 cur[3];
        cur[0] = ok0 ? *reinterpret_cast<const float4*>(qb - WW) : z4;
        cur[1] =       *reinterpret_cast<const float4*>(qb);
        cur[2] = ok2 ? *reinterpret_cast<const float4*>(qb + WW) : z4;

        // Edges via intra-warp shuffle; warp-boundary lanes fix with 1-lane LDG.
        float e0[3], e1[3];
#pragma unroll
        for (int rr = 0; rr < 3; rr++) {
            const bool okr = (rr == 0) ? ok0 : (rr == 2) ? ok2 : true;
            float lft = __shfl_up_sync(0xffffffffu, cur[rr].w, 1);
            float rgt = __shfl_down_sync(0xffffffffu, cur[rr].x, 1);
            if (lfixlane) lft = okr ? qb[(rr - 1) * WW - 1] : 0.f;
            if (rfixlane) rgt = okr ? qb[(rr - 1) * WW + 4] : 0.f;
            e0[rr] = lok ? lft : 0.f;
            e1[rr] = rok ? rgt : 0.f;
        }

        float a0 = 0.f, a1 = 0.f, a2 = 0.f, a3 = 0.f;
#pragma unroll
        for (int di = 0; di < 3; di++) {
            float rowv[6];
            rowv[0] = e0[di];
            rowv[1] = cur[di].x; rowv[2] = cur[di].y;
            rowv[3] = cur[di].z; rowv[4] = cur[di].w;
            rowv[5] = e1[di];
#pragma unroll
            for (int dj = 0; dj < 3; dj++) {
                const int k = di * 3 + dj;
                a0 = fmaf(rowv[dj + 0], fl[0 * KK + k], a0);
                a1 = fmaf(rowv[dj + 1], fl[1 * KK + k], a1);
                a2 = fmaf(rowv[dj + 2], fl[2 * KK + k], a2);
                a3 = fmaf(rowv[dj + 3], fl[3 * KK + k], a3);
            }
        }

        float4 o;
        o.x = fmaxf(a0, 0.0f);
        o.y = fmaxf(a1, 0.0f);
        o.z = fmaxf(a2, 0.0f);
        o.w = fmaxf(a3, 0.0f);
        *reinterpret_cast<float4*>(ob) = o;

        qb += HH * WW;
        ob += HH * WW;
    }
}

extern "C" void kernel_launch(void* const* d_in, const int* in_sizes, int n_in,
                              void* d_out, int out_size)
{
    const float* q  = (const float*)d_in[0];
    const float* df = (const float*)d_in[1];
    const int q_elems = NN * CC * HH * WW;
    if (n_in >= 2 && in_sizes[0] != q_elems) {
        const float* t = q; q = df; df = t;
    }

    float* out = (float*)d_out;

    const int tail    = out_size - q_elems;
    const int tail_n4 = (tail > 0) ? tail / 4 : 0;

    dim3 blk(WQ, TYB);                                        // 192 threads
    dim3 grd(HH / TYB, CC / CG + (tail_n4 > 0 ? 1 : 0), NN);  // 3 x 41 x 8
    dyn_conv_kernel<<<grd, blk>>>(q, df, out, tail_n4);
}

// round 11
// speedup vs baseline: 1.2789x; 1.0617x over previous
#include <cuda_runtime.h>

#define NN 8
#define CC 640
#define HH 48
#define WW 48
#define KK 9
#define WQ 12                 // w-quads per row
#define TYB 16                // h-rows per block
#define THREADS (WQ * TYB)    // 192
#define CG 16                 // channels looped per block (8 pair-iters)

__global__ __launch_bounds__(THREADS, 3) void dyn_conv_kernel(
    const float* __restrict__ q,
    const float* __restrict__ df,
    float* __restrict__ out,
    int tail_n4)
{
    // ---- fused tail-zero slice ----
    if (blockIdx.y == CC / CG) {
        const int q_elems = NN * CC * HH * WW;
        float4* p = reinterpret_cast<float4*>(out + q_elems);
        const int tid    = threadIdx.y * WQ + threadIdx.x;
        const int gtid   = (blockIdx.z * gridDim.x + blockIdx.x) * THREADS + tid;
        const int stride = gridDim.x * gridDim.z * THREADS;
        for (int i = gtid; i < tail_n4; i += stride)
            p[i] = make_float4(0.f, 0.f, 0.f, 0.f);
        return;
    }

    const int tx   = threadIdx.x;                 // 0..11
    const int ty   = threadIdx.y;                 // 0..15
    const int tid  = ty * WQ + tx;
    const int lane = tid & 31;
    const int h    = blockIdx.x * TYB + ty;       // output row
    const int c0   = blockIdx.y * CG;
    const int n    = blockIdx.z;
    const int w4   = tx * 4;

    // Filter for this thread's fixed (h, w4..w4+3), in registers.
    // fl[j*9+k] = tap k for output (h, w4+j); 9 coalesced LDG.128.
    float fl[36];
    {
        const float4* fp = reinterpret_cast<const float4*>(
            df + ((size_t)(n * HH + h) * WW + (size_t)w4) * KK);
#pragma unroll
        for (int v = 0; v < 9; v++) {
            float4 t = fp[v];
            fl[v * 4 + 0] = t.x;
            fl[v * 4 + 1] = t.y;
            fl[v * 4 + 2] = t.z;
            fl[v * 4 + 3] = t.w;
        }
    }

    const bool ok0 = (h - 1) >= 0;
    const bool ok2 = (h + 1) < HH;
    const bool lok = (w4 > 0);
    const bool rok = (w4 + 4 < WW);
    const bool lfixlane = (lane == 0)  && lok;   // row-neighbor in other warp
    const bool rfixlane = (lane == 31) && rok;

    const float* qb = q   + ((size_t)(n * CC + c0) * HH + h) * WW + w4;
    float*       ob = out + ((size_t)(n * CC + c0) * HH + h) * WW + w4;

    const float4 z4 = make_float4(0.f, 0.f, 0.f, 0.f);
    const int CHS = HH * WW;                      // channel stride

    for (int c = 0; c < CG; c += 2) {
        // 6 independent loads in flight (2 channels x 3 rows) -> MLP 6.
        float4 cur[2][3];
#pragma unroll
        for (int p = 0; p < 2; p++) {
            const float* qc = qb + p * CHS;
            cur[p][0] = ok0 ? *reinterpret_cast<const float4*>(qc - WW) : z4;
            cur[p][1] =       *reinterpret_cast<const float4*>(qc);
            cur[p][2] = ok2 ? *reinterpret_cast<const float4*>(qc + WW) : z4;
        }

        // Edges via intra-warp shuffle; warp-boundary lanes fix with 1-lane LDG.
        float e0[2][3], e1[2][3];
#pragma unroll
        for (int p = 0; p < 2; p++) {
            const float* qc = qb + p * CHS;
#pragma unroll
            for (int rr = 0; rr < 3; rr++) {
                const bool okr = (rr == 0) ? ok0 : (rr == 2) ? ok2 : true;
                float lft = __shfl_up_sync(0xffffffffu, cur[p][rr].w, 1);
                float rgt = __shfl_down_sync(0xffffffffu, cur[p][rr].x, 1);
                if (lfixlane) lft = okr ? qc[(rr - 1) * WW - 1] : 0.f;
                if (rfixlane) rgt = okr ? qc[(rr - 1) * WW + 4] : 0.f;
                e0[p][rr] = lok ? lft : 0.f;
                e1[p][rr] = rok ? rgt : 0.f;
            }
        }

        float acc[2][4];
#pragma unroll
        for (int p = 0; p < 2; p++)
#pragma unroll
            for (int j = 0; j < 4; j++) acc[p][j] = 0.0f;

#pragma unroll
        for (int di = 0; di < 3; di++) {
#pragma unroll
            for (int p = 0; p < 2; p++) {
                float rowv[6];
                rowv[0] = e0[p][di];
                rowv[1] = cur[p][di].x; rowv[2] = cur[p][di].y;
                rowv[3] = cur[p][di].z; rowv[4] = cur[p][di].w;
                rowv[5] = e1[p][di];
#pragma unroll
                for (int dj = 0; dj < 3; dj++) {
                    const int k = di * 3 + dj;
                    acc[p][0] = fmaf(rowv[dj + 0], fl[0 * KK + k], acc[p][0]);
                    acc[p][1] = fmaf(rowv[dj + 1], fl[1 * KK + k], acc[p][1]);
                    acc[p][2] = fmaf(rowv[dj + 2], fl[2 * KK + k], acc[p][2]);
                    acc[p][3] = fmaf(rowv[dj + 3], fl[3 * KK + k], acc[p][3]);
                }
            }
        }

#pragma unroll
        for (int p = 0; p < 2; p++) {
            float4 o;
            o.x = fmaxf(acc[p][0], 0.0f);
            o.y = fmaxf(acc[p][1], 0.0f);
            o.z = fmaxf(acc[p][2], 0.0f);
            o.w = fmaxf(acc[p][3], 0.0f);
            *reinterpret_cast<float4*>(ob + p * CHS) = o;
        }

        qb += 2 * CHS;
        ob += 2 * CHS;
    }
}

extern "C" void kernel_launch(void* const* d_in, const int* in_sizes, int n_in,
                              void* d_out, int out_size)
{
    const float* q  = (const float*)d_in[0];
    const float* df = (const float*)d_in[1];
    const int q_elems = NN * CC * HH * WW;
    if (n_in >= 2 && in_sizes[0] != q_elems) {
        const float* t = q; q = df; df = t;
    }

    float* out = (float*)d_out;

    const int tail    = out_size - q_elems;
    const int tail_n4 = (tail > 0) ? tail / 4 : 0;

    dim3 blk(WQ, TYB);                                        // 192 threads
    dim3 grd(HH / TYB, CC / CG + (tail_n4 > 0 ? 1 : 0), NN);  // 3 x 41 x 8
    dyn_conv_kernel<<<grd, blk>>>(q, df, out, tail_n4);
}

// round 12
// speedup vs baseline: 1.3488x; 1.0547x over previous
#include <cuda_runtime.h>

#define NN 8
#define CC 640
#define HH 48
#define WW 48
#define KK 9
#define WQ 12                 // w-quads per row
#define TYB 16                // output rows per block
#define THREADS (WQ * TYB)    // 192
#define CG 8                  // channels per block (staged together)
#define SROWS (TYB + 2)       // 18 staged rows (h0-1 .. h0+16)

__global__ __launch_bounds__(THREADS, 4) void dyn_conv_kernel(
    const float* __restrict__ q,
    const float* __restrict__ df,
    float* __restrict__ out,
    int tail_n4)
{
    __shared__ float qs[CG][SROWS][WW];   // 8*18*48*4 = 27648 B

    // ---- fused tail-zero slice ----
    if (blockIdx.y == CC / CG) {
        const int q_elems = NN * CC * HH * WW;
        float4* p = reinterpret_cast<float4*>(out + q_elems);
        const int tid    = threadIdx.y * WQ + threadIdx.x;
        const int gtid   = (blockIdx.z * gridDim.x + blockIdx.x) * THREADS + tid;
        const int stride = gridDim.x * gridDim.z * THREADS;
        for (int i = gtid; i < tail_n4; i += stride)
            p[i] = make_float4(0.f, 0.f, 0.f, 0.f);
        return;
    }

    const int tx   = threadIdx.x;                 // 0..11
    const int ty   = threadIdx.y;                 // 0..15
    const int tid  = ty * WQ + tx;
    const int lane = tid & 31;
    const int h    = blockIdx.x * TYB + ty;       // this thread's output row
    const int h0m1 = blockIdx.x * TYB - 1;        // global row of staged row 0
    const int c0   = blockIdx.y * CG;
    const int n    = blockIdx.z;
    const int w4   = tx * 4;

    // ---- stage query band: CG channels x 18 rows x 48 w, coalesced ----
    {
        const float4 z4 = make_float4(0.f, 0.f, 0.f, 0.f);
        const float* qbase = q + (size_t)(n * CC + c0) * HH * WW;
#pragma unroll
        for (int it = 0; it < (CG * SROWS * WQ) / THREADS; it++) {   // 9 iters
            int i    = tid + it * THREADS;
            int ch   = i / (SROWS * WQ);
            int rem  = i - ch * (SROWS * WQ);
            int row  = rem / WQ;
            int quad = rem - row * WQ;
            int grow = h0m1 + row;
            float4 v = (grow >= 0 && grow < HH)
                ? *reinterpret_cast<const float4*>(
                      qbase + ((size_t)ch * HH + grow) * WW + quad * 4)
                : z4;
            *reinterpret_cast<float4*>(&qs[ch][row][quad * 4]) = v;
        }
    }

    // ---- filter for this thread's fixed (h, w4..w4+3), in registers ----
    float fl[36];
    {
        const float4* fp = reinterpret_cast<const float4*>(
            df + ((size_t)(n * HH + h) * WW + (size_t)w4) * KK);
#pragma unroll
        for (int v = 0; v < 9; v++) {
            float4 t = fp[v];
            fl[v * 4 + 0] = t.x;
            fl[v * 4 + 1] = t.y;
            fl[v * 4 + 2] = t.z;
            fl[v * 4 + 3] = t.w;
        }
    }

    const bool lok = (w4 > 0);
    const bool rok = (w4 + 4 < WW);
    const bool lfixlane = (lane == 0)  && lok;    // row-neighbor in other warp
    const bool rfixlane = (lane == 31) && rok;

    __syncthreads();

    float* ob = out + ((size_t)(n * CC + c0) * HH + h) * WW + w4;
    const int CHS = HH * WW;

#pragma unroll
    for (int ch = 0; ch < CG; ch++) {
        // operands from smem only: 3 LDS.128 (conflict-free linear pattern)
        float4 cur[3];
#pragma unroll
        for (int di = 0; di < 3; di++)
            cur[di] = *reinterpret_cast<const float4*>(&qs[ch][ty + di][w4]);

        float e0[3], e1[3];
#pragma unroll
        for (int di = 0; di < 3; di++) {
            float lft = __shfl_up_sync(0xffffffffu, cur[di].w, 1);
            float rgt = __shfl_down_sync(0xffffffffu, cur[di].x, 1);
            if (lfixlane) lft = qs[ch][ty + di][w4 - 1];   // smem fixup, cheap
            if (rfixlane) rgt = qs[ch][ty + di][w4 + 4];
            e0[di] = lok ? lft : 0.f;
            e1[di] = rok ? rgt : 0.f;
        }

        float a0 = 0.f, a1 = 0.f, a2 = 0.f, a3 = 0.f;
#pragma unroll
        for (int di = 0; di < 3; di++) {
            float rowv[6];
            rowv[0] = e0[di];
            rowv[1] = cur[di].x; rowv[2] = cur[di].y;
            rowv[3] = cur[di].z; rowv[4] = cur[di].w;
            rowv[5] = e1[di];
#pragma unroll
            for (int dj = 0; dj < 3; dj++) {
                const int k = di * 3 + dj;
                a0 = fmaf(rowv[dj + 0], fl[0 * KK + k], a0);
                a1 = fmaf(rowv[dj + 1], fl[1 * KK + k], a1);
                a2 = fmaf(rowv[dj + 2], fl[2 * KK + k], a2);
                a3 = fmaf(rowv[dj + 3], fl[3 * KK + k], a3);
            }
        }

        float4 o;
        o.x = fmaxf(a0, 0.0f);
        o.y = fmaxf(a1, 0.0f);
        o.z = fmaxf(a2, 0.0f);
        o.w = fmaxf(a3, 0.0f);
        *reinterpret_cast<float4*>(ob + ch * CHS) = o;
    }
}

extern "C" void kernel_launch(void* const* d_in, const int* in_sizes, int n_in,
                              void* d_out, int out_size)
{
    const float* q  = (const float*)d_in[0];
    const float* df = (const float*)d_in[1];
    const int q_elems = NN * CC * HH * WW;
    if (n_in >= 2 && in_sizes[0] != q_elems) {
        const float* t = q; q = df; df = t;
    }

    float* out = (float*)d_out;

    const int tail    = out_size - q_elems;
    const int tail_n4 = (tail > 0) ? tail / 4 : 0;

    dim3 blk(WQ, TYB);                                        // 192 threads
    dim3 grd(HH / TYB, CC / CG + (tail_n4 > 0 ? 1 : 0), NN);  // 3 x 81 x 8
    dyn_conv_kernel<<<grd, blk>>>(q, df, out, tail_n4);
}